// round 11
// baseline (speedup 1.0000x reference)
#include <cuda_runtime.h>
#include <cuda_bf16.h>
#include <stdint.h>
#include <math.h>

#define Bb 8
#define Cc 512
#define Ll 2048
#define CQq 128

// Static device scratch (allocation-free rule: __device__ globals).
__device__ __nv_bfloat16 g_xhi[(size_t)Bb * Ll * Cc];    // x^T split hi [b][pos][c]
__device__ __nv_bfloat16 g_xlo[(size_t)Bb * Ll * Cc];
__device__ __nv_bfloat16 g_wqhi[CQq * Cc];
__device__ __nv_bfloat16 g_wqlo[CQq * Cc];
__device__ __nv_bfloat16 g_wkhi[CQq * Cc];
__device__ __nv_bfloat16 g_wklo[CQq * Cc];
__device__ __nv_bfloat16 g_qhi[(size_t)Bb * Ll * CQq];   // [b][pos][d]
__device__ __nv_bfloat16 g_qlo[(size_t)Bb * Ll * CQq];
__device__ __nv_bfloat16 g_khi[(size_t)Bb * Ll * CQq];
__device__ __nv_bfloat16 g_klo[(size_t)Bb * Ll * CQq];
__device__ float g_v[(size_t)Bb * Cc * Ll];              // gamma!=0 path only
__device__ float g_att[(size_t)Bb * Ll * Ll];            // fallback
__device__ float g_outbuf[(size_t)Bb * Cc * Ll];         // fallback

// 32-wide K chunks in smem, pitch 40 bf16 (80B = 20 words):
// ldmatrix 8-row x 16B reads land on distinct banks (20r mod 32 pattern).
#define KPAD 40
#define T32 (128 * KPAD)              // 5120 bf16 per tile
#define STAGE_ELEMS (4 * T32)         // Ahi,Alo,Bhi,Blo
#define MMA_SMEM_B (2 * STAGE_ELEMS * 2)   // 81920 bytes (2 stages)

// ---------------------------------------------------------------------------
// Split W (CQ x C fp32) into bf16 hi/lo. grid (128, 2), block 128.
// ---------------------------------------------------------------------------
__global__ __launch_bounds__(128)
void wsplit_kernel(const float* __restrict__ q_w, const float* __restrict__ k_w)
{
    const int row = blockIdx.x;
    const int s   = blockIdx.y;
    const float* W = s ? k_w : q_w;
    __nv_bfloat16* ho = s ? g_wkhi : g_wqhi;
    __nv_bfloat16* lo = s ? g_wklo : g_wqlo;

    const int c = threadIdx.x * 4;
    float4 v = *(const float4*)&W[(size_t)row * Cc + c];
    __nv_bfloat16 h[4], l[4];
    float vv[4] = {v.x, v.y, v.z, v.w};
    #pragma unroll
    for (int i = 0; i < 4; i++) {
        h[i] = __float2bfloat16_rn(vv[i]);
        l[i] = __float2bfloat16_rn(vv[i] - __bfloat162float(h[i]));
    }
    *(uint2*)&ho[(size_t)row * Cc + c] = *(uint2*)h;
    *(uint2*)&lo[(size_t)row * Cc + c] = *(uint2*)l;
}

// ---------------------------------------------------------------------------
// Transpose + split x: [b][c][l] fp32 -> [b][l][c] bf16 hi/lo.
// FUSED: when gamma==0, also writes out = x (saves a separate copy kernel).
// ---------------------------------------------------------------------------
__global__ __launch_bounds__(256)
void xsplit_kernel(const float* __restrict__ x, float* __restrict__ out,
                   const float* __restrict__ gamma)
{
    __shared__ float ts[64][65];
    const int b  = blockIdx.z;
    const int l0 = blockIdx.x * 64;
    const int c0 = blockIdx.y * 64;
    const int tid = threadIdx.x;
    const bool docopy = (gamma[0] == 0.0f);

    const float* xb = x + (size_t)b * Cc * Ll;
    float* ob = out + (size_t)b * Cc * Ll;
    const int ly = tid >> 4;          // 0..15
    const int lx = (tid & 15) * 4;    // 0..60
    #pragma unroll
    for (int rr = 0; rr < 4; rr++) {
        const int cl = ly + rr * 16;
        float4 v = *(const float4*)&xb[(size_t)(c0 + cl) * Ll + l0 + lx];
        if (docopy)
            *(float4*)&ob[(size_t)(c0 + cl) * Ll + l0 + lx] = v;
        ts[cl][lx + 0] = v.x;
        ts[cl][lx + 1] = v.y;
        ts[cl][lx + 2] = v.z;
        ts[cl][lx + 3] = v.w;
    }
    __syncthreads();

    __nv_bfloat16* xh = g_xhi + (size_t)b * Ll * Cc;
    __nv_bfloat16* xl = g_xlo + (size_t)b * Ll * Cc;
    const int wy = tid >> 3;          // 0..31
    const int wx = (tid & 7) * 8;     // 0..56
    #pragma unroll
    for (int rr = 0; rr < 2; rr++) {
        const int ll = wy + rr * 32;
        __nv_bfloat16 h[8], l[8];
        #pragma unroll
        for (int e = 0; e < 8; e++) {
            float v = ts[wx + e][ll];
            h[e] = __float2bfloat16_rn(v);
            l[e] = __float2bfloat16_rn(v - __bfloat162float(h[e]));
        }
        *(uint4*)&xh[(size_t)(l0 + ll) * Cc + c0 + wx] = *(uint4*)h;
        *(uint4*)&xl[(size_t)(l0 + ll) * Cc + c0 + wx] = *(uint4*)l;
    }
}

// ---------------------------------------------------------------------------
// mma / ldmatrix / cp.async helpers
// ---------------------------------------------------------------------------
__device__ __forceinline__ void mma16816(float* acc, const uint32_t* a,
                                         const uint32_t* bfr)
{
    asm volatile(
        "mma.sync.aligned.m16n8k16.row.col.f32.bf16.bf16.f32 "
        "{%0,%1,%2,%3}, {%4,%5,%6,%7}, {%8,%9}, {%0,%1,%2,%3};\n"
        : "+f"(acc[0]), "+f"(acc[1]), "+f"(acc[2]), "+f"(acc[3])
        : "r"(a[0]), "r"(a[1]), "r"(a[2]), "r"(a[3]),
          "r"(bfr[0]), "r"(bfr[1]));
}

__device__ __forceinline__ void ldsm_x4(uint32_t* r, uint32_t addr)
{
    asm volatile(
        "ldmatrix.sync.aligned.m8n8.x4.shared.b16 {%0,%1,%2,%3}, [%4];\n"
        : "=r"(r[0]), "=r"(r[1]), "=r"(r[2]), "=r"(r[3]) : "r"(addr));
}

__device__ __forceinline__ void cp16(uint32_t dst, const void* src)
{
    asm volatile("cp.async.cg.shared.global [%0], [%1], 16;\n"
                 :: "r"(dst), "l"(src));
}
#define CP_COMMIT()  asm volatile("cp.async.commit_group;\n" ::: "memory")
#define CP_WAIT1()   asm volatile("cp.async.wait_group 1;\n" ::: "memory")

// per-lane ldmatrix offsets (bf16-element units, relative to tile base)
__device__ __forceinline__ uint32_t a_frag_off(int wm, int lane)
{
    return (uint32_t)((wm * 64 + (lane & 15)) * KPAD + ((lane >> 4) << 3));
}
__device__ __forceinline__ uint32_t b_frag_off(int wn, int lane)
{
    return (uint32_t)((wn * 32 + ((lane >> 4) << 3) + (lane & 7)) * KPAD
                      + (((lane >> 3) & 1) << 3));
}

// ---------------------------------------------------------------------------
// Issue cp.async loads for one 32-wide K chunk into a stage.
// 4 tiles (Ahi,Alo,Bhi,Blo); 2 warps per tile; 8 x 16B per lane.
// ---------------------------------------------------------------------------
__device__ __forceinline__ void issue_chunk(
    uint32_t stageU, int wid, int lane,
    const __nv_bfloat16* s0, const __nv_bfloat16* s1,
    const __nv_bfloat16* s2, const __nv_bfloat16* s3,
    int rowA, int rowB, int stride, int c0)
{
    const int t = wid >> 1;
    const __nv_bfloat16* src = (t == 0) ? s0 : (t == 1) ? s1 : (t == 2) ? s2 : s3;
    const int rbase = (t < 2) ? rowA : rowB;
    const uint32_t dstT = stageU + (uint32_t)(t * T32 * 2);
    #pragma unroll
    for (int rr = 0; rr < 8; rr++) {
        const int u  = rr * 32 + lane;
        const int r  = ((wid & 1) << 6) + (u >> 2);
        const int q4 = u & 3;
        const uint32_t dst = dstT + (uint32_t)(r * KPAD * 2 + q4 * 16);
        cp16(dst, src + (size_t)(rbase + r) * stride + c0 + q4 * 8);
    }
}

// ---------------------------------------------------------------------------
// Compute one 32-wide chunk: 2 k-steps, 3-combo split bf16, ldmatrix frags.
// ---------------------------------------------------------------------------
__device__ __forceinline__ void kchunk32_mma(
    uint32_t stageU, uint32_t a_off, uint32_t b_off, float acc[4][4][4])
{
    const uint32_t AhiU = stageU;
    const uint32_t AloU = stageU + T32 * 2;
    const uint32_t BhiU = stageU + 2 * T32 * 2;
    const uint32_t BloU = stageU + 3 * T32 * 2;
    #pragma unroll
    for (int ks = 0; ks < 2; ks++) {
        const int k0 = ks * 16;
        uint32_t bh[2][4], bl[2][4];
        #pragma unroll
        for (int p = 0; p < 2; p++) {
            const uint32_t bo = 2u * (b_off + (uint32_t)(p * 16 * KPAD + k0));
            ldsm_x4(bh[p], BhiU + bo);
            ldsm_x4(bl[p], BloU + bo);
        }
        #pragma unroll
        for (int am = 0; am < 4; am++) {
            const uint32_t ao = 2u * (a_off + (uint32_t)(am * 16 * KPAD + k0));
            uint32_t ah[4], al[4];
            ldsm_x4(ah, AhiU + ao);
            ldsm_x4(al, AloU + ao);
            #pragma unroll
            for (int bn = 0; bn < 4; bn++) {
                const uint32_t* bhp = &bh[bn >> 1][(bn & 1) * 2];
                const uint32_t* blp = &bl[bn >> 1][(bn & 1) * 2];
                mma16816(acc[am][bn], ah, bhp);
                mma16816(acc[am][bn], ah, blp);
                mma16816(acc[am][bn], al, bhp);
            }
        }
    }
}

// ---------------------------------------------------------------------------
// Pipelined 3-combo split-bf16 GEMM mainloop (2-stage cp.async pipeline).
// ---------------------------------------------------------------------------
template <int NCHUNK>
__device__ __forceinline__ void mma_mainloop(
    uint32_t smU, int wid, int lane,
    const __nv_bfloat16* s0, const __nv_bfloat16* s1,
    const __nv_bfloat16* s2, const __nv_bfloat16* s3,
    int rowA, int rowB, int stride,
    uint32_t a_off, uint32_t b_off, float acc[4][4][4])
{
    issue_chunk(smU, wid, lane, s0, s1, s2, s3, rowA, rowB, stride, 0);
    CP_COMMIT();
    issue_chunk(smU + STAGE_ELEMS * 2, wid, lane, s0, s1, s2, s3,
                rowA, rowB, stride, 32);
    CP_COMMIT();

    #pragma unroll
    for (int it = 0; it < NCHUNK; it++) {
        CP_WAIT1();
        __syncthreads();
        kchunk32_mma(smU + (uint32_t)((it & 1) * STAGE_ELEMS * 2),
                     a_off, b_off, acc);
        __syncthreads();
        if (it + 2 < NCHUNK)
            issue_chunk(smU + (uint32_t)((it & 1) * STAGE_ELEMS * 2),
                        wid, lane, s0, s1, s2, s3, rowA, rowB, stride,
                        (it + 2) * 32);
        CP_COMMIT();   // empty group when drained keeps wait_group 1 correct
    }
}

// ---------------------------------------------------------------------------
// q/k conv on tensor cores: out[pos][d] = sum_c xT[pos][c]*W[d][c] + bias[d]
// grid (L/128, 2 {q,k}, B), block 256 (8 warps, 2m x 4n), K=512 (16 chunks).
// ---------------------------------------------------------------------------
__global__ __launch_bounds__(256, 2)
void qkconv_mma_kernel(const float* __restrict__ q_b, const float* __restrict__ k_b)
{
    extern __shared__ __nv_bfloat16 sm[];
    __shared__ float sbias[128];

    const int p0 = blockIdx.x * 128;
    const int s  = blockIdx.y;
    const int b  = blockIdx.z;

    const __nv_bfloat16* whi = s ? g_wkhi : g_wqhi;
    const __nv_bfloat16* wlo = s ? g_wklo : g_wqlo;
    const float* bias = s ? k_b : q_b;

    const int tid  = threadIdx.x;
    const int lane = tid & 31;
    const int wid  = tid >> 5;
    const int wm   = wid >> 2;
    const int wn   = wid & 3;
    const int g    = lane >> 2;
    const int t    = lane & 3;

    if (tid < 128) sbias[tid] = bias[tid];

    const uint32_t smU = (uint32_t)__cvta_generic_to_shared(sm);
    const uint32_t a_off = a_frag_off(wm, lane);
    const uint32_t b_off = b_frag_off(wn, lane);

    const __nv_bfloat16* xh = g_xhi + (size_t)b * Ll * Cc;
    const __nv_bfloat16* xl = g_xlo + (size_t)b * Ll * Cc;

    float acc[4][4][4];
    #pragma unroll
    for (int am = 0; am < 4; am++)
        #pragma unroll
        for (int bn = 0; bn < 4; bn++)
            #pragma unroll
            for (int c = 0; c < 4; c++) acc[am][bn][c] = 0.0f;

    mma_mainloop<16>(smU, wid, lane, xh, xl, whi, wlo, p0, 0, Cc,
                     a_off, b_off, acc);

    __nv_bfloat16* hb = (s ? g_khi : g_qhi) + (size_t)b * Ll * CQq;
    __nv_bfloat16* lb = (s ? g_klo : g_qlo) + (size_t)b * Ll * CQq;
    #pragma unroll
    for (int am = 0; am < 4; am++) {
        const int r0 = wm * 64 + am * 16 + g;
        #pragma unroll
        for (int bn = 0; bn < 4; bn++) {
            const int col = wn * 32 + bn * 8 + 2 * t;
            const float b0 = sbias[col], b1 = sbias[col + 1];
            #pragma unroll
            for (int half = 0; half < 2; half++) {
                const int row = r0 + half * 8;
                const float v0 = acc[am][bn][half * 2 + 0] + b0;
                const float v1 = acc[am][bn][half * 2 + 1] + b1;
                __nv_bfloat16 h0 = __float2bfloat16_rn(v0);
                __nv_bfloat16 h1 = __float2bfloat16_rn(v1);
                __nv_bfloat16 l0 = __float2bfloat16_rn(v0 - __bfloat162float(h0));
                __nv_bfloat16 l1 = __float2bfloat16_rn(v1 - __bfloat162float(h1));
                *(__nv_bfloat162*)&hb[(size_t)(p0 + row) * CQq + col] =
                    __halves2bfloat162(h0, h1);
                *(__nv_bfloat162*)&lb[(size_t)(p0 + row) * CQq + col] =
                    __halves2bfloat162(l0, l1);
            }
        }
    }
}

// ---------------------------------------------------------------------------
// energy[b,i,j] = sum_d q[b,i,d]*k[b,j,d], K=128 (4 chunks), pipelined.
// ---------------------------------------------------------------------------
__global__ __launch_bounds__(256, 2)
void energy_mma_kernel(float* __restrict__ E)
{
    extern __shared__ __nv_bfloat16 sm[];

    const int b  = blockIdx.z;
    const int i0 = blockIdx.y * 128;
    const int j0 = blockIdx.x * 128;

    const int tid  = threadIdx.x;
    const int lane = tid & 31;
    const int wid  = tid >> 5;
    const int wm   = wid >> 2;
    const int wn   = wid & 3;
    const int g    = lane >> 2;
    const int t    = lane & 3;

    const uint32_t smU = (uint32_t)__cvta_generic_to_shared(sm);
    const uint32_t a_off = a_frag_off(wm, lane);
    const uint32_t b_off = b_frag_off(wn, lane);

    const size_t boff = (size_t)b * Ll * CQq;

    float acc[4][4][4];
    #pragma unroll
    for (int am = 0; am < 4; am++)
        #pragma unroll
        for (int bn = 0; bn < 4; bn++)
            #pragma unroll
            for (int c = 0; c < 4; c++) acc[am][bn][c] = 0.0f;

    mma_mainloop<4>(smU, wid, lane, g_qhi + boff, g_qlo + boff,
                    g_khi + boff, g_klo + boff, i0, j0, CQq,
                    a_off, b_off, acc);

    float* eb = E + (size_t)b * Ll * Ll;
    #pragma unroll
    for (int am = 0; am < 4; am++) {
        const int row = i0 + wm * 64 + am * 16 + g;
        #pragma unroll
        for (int bn = 0; bn < 4; bn++) {
            const int col = j0 + wn * 32 + bn * 8 + 2 * t;
            *(float2*)&eb[(size_t)row * Ll + col] =
                make_float2(acc[am][bn][0], acc[am][bn][1]);
            *(float2*)&eb[(size_t)(row + 8) * Ll + col] =
                make_float2(acc[am][bn][2], acc[am][bn][3]);
        }
    }
}

// ---------------------------------------------------------------------------
// In-place row softmax, float4 loads + warp-shuffle reductions.
// ---------------------------------------------------------------------------
__global__ __launch_bounds__(256)
void softmax_kernel(float* __restrict__ att)
{
    const size_t row = blockIdx.x;
    float4* p = (float4*)(att + row * (size_t)Ll);
    const int tid = threadIdx.x;
    const int lane = tid & 31, wrp = tid >> 5;

    float4 v0 = p[tid];
    float4 v1 = p[tid + 256];

    float m = fmaxf(fmaxf(fmaxf(v0.x, v0.y), fmaxf(v0.z, v0.w)),
                    fmaxf(fmaxf(v1.x, v1.y), fmaxf(v1.z, v1.w)));
    #pragma unroll
    for (int s = 16; s > 0; s >>= 1)
        m = fmaxf(m, __shfl_xor_sync(0xffffffffu, m, s));

    __shared__ float red[8];
    if (lane == 0) red[wrp] = m;
    __syncthreads();
    float bm = red[lane & 7];
    #pragma unroll
    for (int s = 4; s > 0; s >>= 1)
        bm = fmaxf(bm, __shfl_xor_sync(0xffffffffu, bm, s));
    m = __shfl_sync(0xffffffffu, bm, 0);

    v0.x = __expf(v0.x - m); v0.y = __expf(v0.y - m);
    v0.z = __expf(v0.z - m); v0.w = __expf(v0.w - m);
    v1.x = __expf(v1.x - m); v1.y = __expf(v1.y - m);
    v1.z = __expf(v1.z - m); v1.w = __expf(v1.w - m);

    float sum = v0.x + v0.y + v0.z + v0.w + v1.x + v1.y + v1.z + v1.w;
    #pragma unroll
    for (int s = 16; s > 0; s >>= 1)
        sum += __shfl_xor_sync(0xffffffffu, sum, s);
    __syncthreads();
    if (lane == 0) red[wrp] = sum;
    __syncthreads();
    float bs = red[lane & 7];
    #pragma unroll
    for (int s = 4; s > 0; s >>= 1)
        bs += __shfl_xor_sync(0xffffffffu, bs, s);
    const float inv = 1.0f / __shfl_sync(0xffffffffu, bs, 0);

    v0.x *= inv; v0.y *= inv; v0.z *= inv; v0.w *= inv;
    v1.x *= inv; v1.y *= inv; v1.z *= inv; v1.w *= inv;
    p[tid]       = v0;
    p[tid + 256] = v1;
}

// ---------------------------------------------------------------------------
// gamma != 0 path kernels (gated; full-precision fallback).
// ---------------------------------------------------------------------------
__global__ __launch_bounds__(256)
void vconv_kernel(const float* __restrict__ W, const float* __restrict__ bias,
                  const float* __restrict__ x, float* __restrict__ out,
                  const float* __restrict__ gamma)
{
    if (gamma[0] == 0.0f) return;
    const int b  = blockIdx.z;
    const int m0 = blockIdx.y * 128;
    const int n0 = blockIdx.x * 128;

    __shared__ float As[8][128];
    __shared__ float Bs[8][128];

    const int tid = threadIdx.x;
    const int tx = tid % 16, ty = tid / 16;
    const float* xb = x + (size_t)b * Cc * Ll;

    const int aRow = tid >> 1;
    const int aCol = (tid & 1) * 4;
    const int bRow = tid >> 5;
    const int bCol = (tid & 31) * 4;

    float acc[8][8];
    #pragma unroll
    for (int i = 0; i < 8; i++)
        #pragma unroll
        for (int j = 0; j < 8; j++) acc[i][j] = 0.0f;

    for (int k0 = 0; k0 < Cc; k0 += 8) {
        float4 a = *(const float4*)&W[(size_t)(m0 + aRow) * Cc + k0 + aCol];
        As[aCol + 0][aRow] = a.x;
        As[aCol + 1][aRow] = a.y;
        As[aCol + 2][aRow] = a.z;
        As[aCol + 3][aRow] = a.w;
        *(float4*)&Bs[bRow][bCol] =
            *(const float4*)&xb[(size_t)(k0 + bRow) * Ll + n0 + bCol];
        __syncthreads();

        #pragma unroll
        for (int k = 0; k < 8; k++) {
            float rm[8], rn[8];
            #pragma unroll
            for (int i = 0; i < 8; i++) rm[i] = As[k][ty * 8 + i];
            #pragma unroll
            for (int j = 0; j < 8; j++) rn[j] = Bs[k][tx * 8 + j];
            #pragma unroll
            for (int i = 0; i < 8; i++)
                #pragma unroll
                for (int j = 0; j < 8; j++)
                    acc[i][j] = fmaf(rm[i], rn[j], acc[i][j]);
        }
        __syncthreads();
    }

    float* ob = out + (size_t)b * Cc * Ll;
    #pragma unroll
    for (int i = 0; i < 8; i++) {
        const int m = m0 + ty * 8 + i;
        const float bb = bias[m];
        float* po = ob + (size_t)m * Ll + n0 + tx * 8;
        *(float4*)po = make_float4(acc[i][0] + bb, acc[i][1] + bb,
                                   acc[i][2] + bb, acc[i][3] + bb);
        *(float4*)(po + 4) = make_float4(acc[i][4] + bb, acc[i][5] + bb,
                                         acc[i][6] + bb, acc[i][7] + bb);
    }
}

__global__ __launch_bounds__(256)
void outgemm_kernel(const float* __restrict__ att, const float* __restrict__ x,
                    float* __restrict__ out, const float* __restrict__ gamma)
{
    const float g = gamma[0];
    if (g == 0.0f) return;
    const int b  = blockIdx.z;
    const int c0 = blockIdx.y * 128;
    const int i0 = blockIdx.x * 128;

    __shared__ float Vs[8][128];
    __shared__ float Ts[8][128];

    const int tid = threadIdx.x;
    const int tx = tid % 16, ty = tid / 16;
    const int aRow = tid >> 1;
    const int aCol = (tid & 1) * 4;

    const float* vb = g_v + (size_t)b * Cc * Ll;
    const float* ab = att + (size_t)b * Ll * Ll;

    float acc[8][8];
    #pragma unroll
    for (int i = 0; i < 8; i++)
        #pragma unroll
        for (int j = 0; j < 8; j++) acc[i][j] = 0.0f;

    for (int j0 = 0; j0 < Ll; j0 += 8) {
        float4 a = *(const float4*)&vb[(size_t)(c0 + aRow) * Ll + j0 + aCol];
        Vs[aCol + 0][aRow] = a.x;
        Vs[aCol + 1][aRow] = a.y;
        Vs[aCol + 2][aRow] = a.z;
        Vs[aCol + 3][aRow] = a.w;
        float4 tt = *(const float4*)&ab[(size_t)(i0 + aRow) * Ll + j0 + aCol];
        Ts[aCol + 0][aRow] = tt.x;
        Ts[aCol + 1][aRow] = tt.y;
        Ts[aCol + 2][aRow] = tt.z;
        Ts[aCol + 3][aRow] = tt.w;
        __syncthreads();

        #pragma unroll
        for (int k = 0; k < 8; k++) {
            float rm[8], rn[8];
            #pragma unroll
            for (int i = 0; i < 8; i++) rm[i] = Vs[k][ty * 8 + i];
            #pragma unroll
            for (int j = 0; j < 8; j++) rn[j] = Ts[k][tx * 8 + j];
            #pragma unroll
            for (int i = 0; i < 8; i++)
                #pragma unroll
                for (int j = 0; j < 8; j++)
                    acc[i][j] = fmaf(rm[i], rn[j], acc[i][j]);
        }
        __syncthreads();
    }

    #pragma unroll
    for (int i = 0; i < 8; i++) {
        const size_t off = (size_t)b * Cc * Ll + (size_t)(c0 + ty * 8 + i) * Ll
                         + i0 + tx * 8;
        #pragma unroll
        for (int j = 0; j < 8; j++)
            out[off + j] = g * acc[i][j] + x[off + j];
    }
}

// ---------------------------------------------------------------------------
extern "C" void kernel_launch(void* const* d_in, const int* in_sizes, int n_in,
                              void* d_out, int out_size)
{
    (void)in_sizes; (void)n_in;
    const float* x     = (const float*)d_in[0];
    const float* q_w   = (const float*)d_in[1];
    const float* q_b   = (const float*)d_in[2];
    const float* k_w   = (const float*)d_in[3];
    const float* k_b   = (const float*)d_in[4];
    const float* v_w   = (const float*)d_in[5];
    const float* v_b   = (const float*)d_in[6];
    const float* gamma = (const float*)d_in[7];

    const size_t BCL = (size_t)Bb * Cc * Ll;        // 8388608
    const size_t BLL = (size_t)Bb * Ll * Ll;        // 33554432

    float* out_ptr;
    float* att_ptr;
    if ((size_t)out_size >= BCL + BLL) {
        out_ptr = (float*)d_out;
        att_ptr = (float*)d_out + BCL;
    } else if ((size_t)out_size == BLL) {
        cudaGetSymbolAddress((void**)&out_ptr, g_outbuf);
        att_ptr = (float*)d_out;
    } else {
        out_ptr = (float*)d_out;
        cudaGetSymbolAddress((void**)&att_ptr, g_att);
    }
    float* vbuf; cudaGetSymbolAddress((void**)&vbuf, g_v);

    static int smem_set = 0;
    if (!smem_set) {
        cudaFuncSetAttribute(energy_mma_kernel,
                             cudaFuncAttributeMaxDynamicSharedMemorySize,
                             MMA_SMEM_B);
        cudaFuncSetAttribute(qkconv_mma_kernel,
                             cudaFuncAttributeMaxDynamicSharedMemorySize,
                             MMA_SMEM_B);
        smem_set = 1;
    }

    dim3 blk(256);

    // split inputs for tensor-core path (xsplit also does out=x when gamma==0)
    wsplit_kernel<<<dim3(CQq, 2), dim3(128)>>>(q_w, k_w);
    xsplit_kernel<<<dim3(Ll / 64, Cc / 64, Bb), blk>>>(x, out_ptr, gamma);

    // q and k projections on tensor cores -> split bf16 [pos][d]
    qkconv_mma_kernel<<<dim3(Ll / 128, 2, Bb), blk, MMA_SMEM_B>>>(q_b, k_b);

    // energy on tensor cores -> attention region, softmax in place
    energy_mma_kernel<<<dim3(Ll / 128, Ll / 128, Bb), blk, MMA_SMEM_B>>>(att_ptr);
    softmax_kernel<<<dim3(Bb * Ll), blk>>>(att_ptr);

    // gamma != 0 fallback path (no-ops when gamma == 0)
    vconv_kernel<<<dim3(Ll / 128, Cc / 128, Bb), blk>>>(v_w, v_b, x, vbuf, gamma);
    outgemm_kernel<<<dim3(Ll / 128, Cc / 128, Bb), blk>>>(att_ptr, x, out_ptr, gamma);
}

// round 12
// speedup vs baseline: 1.0552x; 1.0552x over previous
#include <cuda_runtime.h>
#include <cuda_bf16.h>
#include <stdint.h>
#include <math.h>

#define Bb 8
#define Cc 512
#define Ll 2048
#define CQq 128

// Static device scratch (allocation-free rule: __device__ globals).
__device__ __nv_bfloat16 g_xhi[(size_t)Bb * Ll * Cc];    // x^T split hi [b][pos][c]
__device__ __nv_bfloat16 g_xlo[(size_t)Bb * Ll * Cc];
__device__ __nv_bfloat16 g_wqhi[CQq * Cc];
__device__ __nv_bfloat16 g_wqlo[CQq * Cc];
__device__ __nv_bfloat16 g_wkhi[CQq * Cc];
__device__ __nv_bfloat16 g_wklo[CQq * Cc];
__device__ __nv_bfloat16 g_qhi[(size_t)Bb * Ll * CQq];   // [b][pos][d]
__device__ __nv_bfloat16 g_qlo[(size_t)Bb * Ll * CQq];
__device__ __nv_bfloat16 g_khi[(size_t)Bb * Ll * CQq];
__device__ __nv_bfloat16 g_klo[(size_t)Bb * Ll * CQq];
__device__ float g_v[(size_t)Bb * Cc * Ll];              // gamma!=0 path only
__device__ float g_att[(size_t)Bb * Ll * Ll];            // fallback
__device__ float g_outbuf[(size_t)Bb * Cc * Ll];         // fallback

// smem tile pitch for 64-wide bf16 chunks: 72 -> ldmatrix 8-row x 16B reads
// cover all 32 banks exactly once (conflict-free).
#define CPAD 72
#define TILE_HW (128 * CPAD)   // bf16 elements per tile
#define MMA_SMEM_B (4 * TILE_HW * 2)   // 73728 bytes

// ---------------------------------------------------------------------------
// Split W (CQ x C fp32) into bf16 hi/lo. grid (128, 2), block 128.
// ---------------------------------------------------------------------------
__global__ __launch_bounds__(128)
void wsplit_kernel(const float* __restrict__ q_w, const float* __restrict__ k_w)
{
    const int row = blockIdx.x;
    const int s   = blockIdx.y;
    const float* W = s ? k_w : q_w;
    __nv_bfloat16* ho = s ? g_wkhi : g_wqhi;
    __nv_bfloat16* lo = s ? g_wklo : g_wqlo;

    const int c = threadIdx.x * 4;
    float4 v = *(const float4*)&W[(size_t)row * Cc + c];
    __nv_bfloat16 h[4], l[4];
    float vv[4] = {v.x, v.y, v.z, v.w};
    #pragma unroll
    for (int i = 0; i < 4; i++) {
        h[i] = __float2bfloat16_rn(vv[i]);
        l[i] = __float2bfloat16_rn(vv[i] - __bfloat162float(h[i]));
    }
    *(uint2*)&ho[(size_t)row * Cc + c] = *(uint2*)h;
    *(uint2*)&lo[(size_t)row * Cc + c] = *(uint2*)l;
}

// ---------------------------------------------------------------------------
// Transpose + split x: [b][c][l] fp32 -> [b][l][c] bf16 hi/lo.
// FUSED: when gamma==0, also writes out = x (saves a separate copy kernel).
// ---------------------------------------------------------------------------
__global__ __launch_bounds__(256)
void xsplit_kernel(const float* __restrict__ x, float* __restrict__ out,
                   const float* __restrict__ gamma)
{
    __shared__ float ts[64][65];
    const int b  = blockIdx.z;
    const int l0 = blockIdx.x * 64;
    const int c0 = blockIdx.y * 64;
    const int tid = threadIdx.x;
    const bool docopy = (gamma[0] == 0.0f);

    const float* xb = x + (size_t)b * Cc * Ll;
    float* ob = out + (size_t)b * Cc * Ll;
    const int ly = tid >> 4;          // 0..15
    const int lx = (tid & 15) * 4;    // 0..60
    #pragma unroll
    for (int rr = 0; rr < 4; rr++) {
        const int cl = ly + rr * 16;
        float4 v = *(const float4*)&xb[(size_t)(c0 + cl) * Ll + l0 + lx];
        if (docopy)
            *(float4*)&ob[(size_t)(c0 + cl) * Ll + l0 + lx] = v;
        ts[cl][lx + 0] = v.x;
        ts[cl][lx + 1] = v.y;
        ts[cl][lx + 2] = v.z;
        ts[cl][lx + 3] = v.w;
    }
    __syncthreads();

    __nv_bfloat16* xh = g_xhi + (size_t)b * Ll * Cc;
    __nv_bfloat16* xl = g_xlo + (size_t)b * Ll * Cc;
    const int wy = tid >> 3;          // 0..31
    const int wx = (tid & 7) * 8;     // 0..56
    #pragma unroll
    for (int rr = 0; rr < 2; rr++) {
        const int ll = wy + rr * 32;
        __nv_bfloat16 h[8], l[8];
        #pragma unroll
        for (int e = 0; e < 8; e++) {
            float v = ts[wx + e][ll];
            h[e] = __float2bfloat16_rn(v);
            l[e] = __float2bfloat16_rn(v - __bfloat162float(h[e]));
        }
        *(uint4*)&xh[(size_t)(l0 + ll) * Cc + c0 + wx] = *(uint4*)h;
        *(uint4*)&xl[(size_t)(l0 + ll) * Cc + c0 + wx] = *(uint4*)l;
    }
}

// ---------------------------------------------------------------------------
// mma / ldmatrix / cp.async helpers
// ---------------------------------------------------------------------------
__device__ __forceinline__ void mma16816(float* acc, const uint32_t* a,
                                         const uint32_t* bfr)
{
    asm volatile(
        "mma.sync.aligned.m16n8k16.row.col.f32.bf16.bf16.f32 "
        "{%0,%1,%2,%3}, {%4,%5,%6,%7}, {%8,%9}, {%0,%1,%2,%3};\n"
        : "+f"(acc[0]), "+f"(acc[1]), "+f"(acc[2]), "+f"(acc[3])
        : "r"(a[0]), "r"(a[1]), "r"(a[2]), "r"(a[3]),
          "r"(bfr[0]), "r"(bfr[1]));
}

__device__ __forceinline__ void ldsm_x4(uint32_t* r, uint32_t addr)
{
    asm volatile(
        "ldmatrix.sync.aligned.m8n8.x4.shared.b16 {%0,%1,%2,%3}, [%4];\n"
        : "=r"(r[0]), "=r"(r[1]), "=r"(r[2]), "=r"(r[3]) : "r"(addr));
}

__device__ __forceinline__ void cp16(uint32_t dst, const void* src)
{
    asm volatile("cp.async.cg.shared.global [%0], [%1], 16;\n"
                 :: "r"(dst), "l"(src));
}
#define CP_WAIT_ALL() asm volatile("cp.async.wait_all;\n" ::: "memory")

// per-lane ldmatrix offsets (bf16-element units, relative to tile base)
__device__ __forceinline__ uint32_t a_frag_off(int wm, int lane)
{
    return (uint32_t)((wm * 64 + (lane & 15)) * CPAD + ((lane >> 4) << 3));
}
__device__ __forceinline__ uint32_t b_frag_off(int wn, int lane)
{
    return (uint32_t)((wn * 32 + ((lane >> 4) << 3) + (lane & 7)) * CPAD
                      + (((lane >> 3) & 1) << 3));
}

// ---------------------------------------------------------------------------
// cp.async loads for one 64-wide K chunk (4 tiles: Ahi,Alo,Bhi,Blo).
// Each thread: 4 iterations x 4 tiles x 16B.
// ---------------------------------------------------------------------------
__device__ __forceinline__ void load_chunk_async(
    uint32_t smU, int tid,
    const __nv_bfloat16* aH, const __nv_bfloat16* aL,
    const __nv_bfloat16* bH, const __nv_bfloat16* bL,
    int rowA, int rowB, int stride, int c0)
{
    #pragma unroll
    for (int q = 0; q < 4; q++) {
        const int idx = q * 256 + tid;
        const int r  = idx >> 3;          // 0..127
        const int cc = (idx & 7) * 8;     // 0..56
        const uint32_t d = smU + (uint32_t)((r * CPAD + cc) * 2);
        cp16(d,                   aH + (size_t)(rowA + r) * stride + c0 + cc);
        cp16(d + TILE_HW * 2,     aL + (size_t)(rowA + r) * stride + c0 + cc);
        cp16(d + 2 * TILE_HW * 2, bH + (size_t)(rowB + r) * stride + c0 + cc);
        cp16(d + 3 * TILE_HW * 2, bL + (size_t)(rowB + r) * stride + c0 + cc);
    }
}

// ---------------------------------------------------------------------------
// Compute one 64-wide chunk: 4 k-steps, 3-combo split bf16, ldmatrix frags.
// ---------------------------------------------------------------------------
__device__ __forceinline__ void kchunk_mma(
    uint32_t smU, uint32_t a_off, uint32_t b_off, float acc[4][4][4])
{
    const uint32_t AhiU = smU;
    const uint32_t AloU = smU + TILE_HW * 2;
    const uint32_t BhiU = smU + 2 * TILE_HW * 2;
    const uint32_t BloU = smU + 3 * TILE_HW * 2;
    #pragma unroll
    for (int ks = 0; ks < 4; ks++) {
        const int k0 = ks * 16;
        uint32_t bh[2][4], bl[2][4];   // [pair p][4 regs = bn=2p, 2p+1]
        #pragma unroll
        for (int p = 0; p < 2; p++) {
            const uint32_t bo = 2u * (b_off + (uint32_t)(p * 16 * CPAD + k0));
            ldsm_x4(bh[p], BhiU + bo);
            ldsm_x4(bl[p], BloU + bo);
        }
        #pragma unroll
        for (int am = 0; am < 4; am++) {
            const uint32_t ao = 2u * (a_off + (uint32_t)(am * 16 * CPAD + k0));
            uint32_t ah[4], al[4];
            ldsm_x4(ah, AhiU + ao);
            ldsm_x4(al, AloU + ao);
            #pragma unroll
            for (int bn = 0; bn < 4; bn++) {
                const uint32_t* bhp = &bh[bn >> 1][(bn & 1) * 2];
                const uint32_t* blp = &bl[bn >> 1][(bn & 1) * 2];
                mma16816(acc[am][bn], ah, bhp);
                mma16816(acc[am][bn], ah, blp);
                mma16816(acc[am][bn], al, bhp);
            }
        }
    }
}

// ---------------------------------------------------------------------------
// q/k conv on tensor cores: out[pos][d] = sum_c xT[pos][c]*W[d][c] + bias[d]
// grid (L/128, 2 {q,k}, B), block 256 (8 warps, 2m x 4n), K=512 in 8 chunks.
// ---------------------------------------------------------------------------
__global__ __launch_bounds__(256, 2)
void qkconv_mma_kernel(const float* __restrict__ q_b, const float* __restrict__ k_b)
{
    extern __shared__ __nv_bfloat16 sm[];
    __shared__ float sbias[128];

    const int p0 = blockIdx.x * 128;
    const int s  = blockIdx.y;
    const int b  = blockIdx.z;

    const __nv_bfloat16* whi = s ? g_wkhi : g_wqhi;
    const __nv_bfloat16* wlo = s ? g_wklo : g_wqlo;
    const float* bias = s ? k_b : q_b;

    const int tid  = threadIdx.x;
    const int lane = tid & 31;
    const int wid  = tid >> 5;
    const int wm   = wid >> 2;
    const int wn   = wid & 3;
    const int g    = lane >> 2;
    const int t    = lane & 3;

    if (tid < 128) sbias[tid] = bias[tid];

    const uint32_t smU = (uint32_t)__cvta_generic_to_shared(sm);
    const uint32_t a_off = a_frag_off(wm, lane);
    const uint32_t b_off = b_frag_off(wn, lane);

    const __nv_bfloat16* xh = g_xhi + (size_t)b * Ll * Cc;
    const __nv_bfloat16* xl = g_xlo + (size_t)b * Ll * Cc;

    float acc[4][4][4];
    #pragma unroll
    for (int am = 0; am < 4; am++)
        #pragma unroll
        for (int bn = 0; bn < 4; bn++)
            #pragma unroll
            for (int c = 0; c < 4; c++) acc[am][bn][c] = 0.0f;

    for (int it = 0; it < 8; it++) {
        if (it) __syncthreads();
        load_chunk_async(smU, tid, xh, xl, whi, wlo, p0, 0, Cc, it * 64);
        CP_WAIT_ALL();
        __syncthreads();
        kchunk_mma(smU, a_off, b_off, acc);
    }

    __nv_bfloat16* hb = (s ? g_khi : g_qhi) + (size_t)b * Ll * CQq;
    __nv_bfloat16* lb = (s ? g_klo : g_qlo) + (size_t)b * Ll * CQq;
    #pragma unroll
    for (int am = 0; am < 4; am++) {
        const int r0 = wm * 64 + am * 16 + g;
        #pragma unroll
        for (int bn = 0; bn < 4; bn++) {
            const int col = wn * 32 + bn * 8 + 2 * t;
            const float b0 = sbias[col], b1 = sbias[col + 1];
            #pragma unroll
            for (int half = 0; half < 2; half++) {
                const int row = r0 + half * 8;
                const float v0 = acc[am][bn][half * 2 + 0] + b0;
                const float v1 = acc[am][bn][half * 2 + 1] + b1;
                __nv_bfloat16 h0 = __float2bfloat16_rn(v0);
                __nv_bfloat16 h1 = __float2bfloat16_rn(v1);
                __nv_bfloat16 l0 = __float2bfloat16_rn(v0 - __bfloat162float(h0));
                __nv_bfloat16 l1 = __float2bfloat16_rn(v1 - __bfloat162float(h1));
                *(__nv_bfloat162*)&hb[(size_t)(p0 + row) * CQq + col] =
                    __halves2bfloat162(h0, h1);
                *(__nv_bfloat162*)&lb[(size_t)(p0 + row) * CQq + col] =
                    __halves2bfloat162(l0, l1);
            }
        }
    }
}

// ---------------------------------------------------------------------------
// energy[b,i,j] = sum_d q[b,i,d]*k[b,j,d], split-bf16 3-combo, ldmatrix frags.
// K=128 in 2 chunks of 64. Round-10 serialized structure + cp.async loads.
// ---------------------------------------------------------------------------
__global__ __launch_bounds__(256, 2)
void energy_mma_kernel(float* __restrict__ E)
{
    extern __shared__ __nv_bfloat16 sm[];

    const int b  = blockIdx.z;
    const int i0 = blockIdx.y * 128;
    const int j0 = blockIdx.x * 128;

    const int tid  = threadIdx.x;
    const int lane = tid & 31;
    const int wid  = tid >> 5;
    const int wm   = wid >> 2;
    const int wn   = wid & 3;
    const int g    = lane >> 2;
    const int t    = lane & 3;

    const uint32_t smU = (uint32_t)__cvta_generic_to_shared(sm);
    const uint32_t a_off = a_frag_off(wm, lane);
    const uint32_t b_off = b_frag_off(wn, lane);

    const size_t boff = (size_t)b * Ll * CQq;
    const __nv_bfloat16* qh = g_qhi + boff;
    const __nv_bfloat16* ql = g_qlo + boff;
    const __nv_bfloat16* kh = g_khi + boff;
    const __nv_bfloat16* kl = g_klo + boff;

    float acc[4][4][4];
    #pragma unroll
    for (int am = 0; am < 4; am++)
        #pragma unroll
        for (int bn = 0; bn < 4; bn++)
            #pragma unroll
            for (int c = 0; c < 4; c++) acc[am][bn][c] = 0.0f;

    #pragma unroll
    for (int it = 0; it < 2; it++) {
        if (it) __syncthreads();
        load_chunk_async(smU, tid, qh, ql, kh, kl, i0, j0, CQq, it * 64);
        CP_WAIT_ALL();
        __syncthreads();
        kchunk_mma(smU, a_off, b_off, acc);
    }

    float* eb = E + (size_t)b * Ll * Ll;
    #pragma unroll
    for (int am = 0; am < 4; am++) {
        const int row = i0 + wm * 64 + am * 16 + g;
        #pragma unroll
        for (int bn = 0; bn < 4; bn++) {
            const int col = j0 + wn * 32 + bn * 8 + 2 * t;
            *(float2*)&eb[(size_t)row * Ll + col] =
                make_float2(acc[am][bn][0], acc[am][bn][1]);
            *(float2*)&eb[(size_t)(row + 8) * Ll + col] =
                make_float2(acc[am][bn][2], acc[am][bn][3]);
        }
    }
}

// ---------------------------------------------------------------------------
// In-place row softmax, float4 loads + warp-shuffle reductions.
// ---------------------------------------------------------------------------
__global__ __launch_bounds__(256)
void softmax_kernel(float* __restrict__ att)
{
    const size_t row = blockIdx.x;
    float4* p = (float4*)(att + row * (size_t)Ll);
    const int tid = threadIdx.x;
    const int lane = tid & 31, wrp = tid >> 5;

    float4 v0 = p[tid];
    float4 v1 = p[tid + 256];

    float m = fmaxf(fmaxf(fmaxf(v0.x, v0.y), fmaxf(v0.z, v0.w)),
                    fmaxf(fmaxf(v1.x, v1.y), fmaxf(v1.z, v1.w)));
    #pragma unroll
    for (int s = 16; s > 0; s >>= 1)
        m = fmaxf(m, __shfl_xor_sync(0xffffffffu, m, s));

    __shared__ float red[8];
    if (lane == 0) red[wrp] = m;
    __syncthreads();
    float bm = red[lane & 7];
    #pragma unroll
    for (int s = 4; s > 0; s >>= 1)
        bm = fmaxf(bm, __shfl_xor_sync(0xffffffffu, bm, s));
    m = __shfl_sync(0xffffffffu, bm, 0);

    v0.x = __expf(v0.x - m); v0.y = __expf(v0.y - m);
    v0.z = __expf(v0.z - m); v0.w = __expf(v0.w - m);
    v1.x = __expf(v1.x - m); v1.y = __expf(v1.y - m);
    v1.z = __expf(v1.z - m); v1.w = __expf(v1.w - m);

    float sum = v0.x + v0.y + v0.z + v0.w + v1.x + v1.y + v1.z + v1.w;
    #pragma unroll
    for (int s = 16; s > 0; s >>= 1)
        sum += __shfl_xor_sync(0xffffffffu, sum, s);
    __syncthreads();
    if (lane == 0) red[wrp] = sum;
    __syncthreads();
    float bs = red[lane & 7];
    #pragma unroll
    for (int s = 4; s > 0; s >>= 1)
        bs += __shfl_xor_sync(0xffffffffu, bs, s);
    const float inv = 1.0f / __shfl_sync(0xffffffffu, bs, 0);

    v0.x *= inv; v0.y *= inv; v0.z *= inv; v0.w *= inv;
    v1.x *= inv; v1.y *= inv; v1.z *= inv; v1.w *= inv;
    p[tid]       = v0;
    p[tid + 256] = v1;
}

// ---------------------------------------------------------------------------
// gamma != 0 path kernels (gated; full-precision fallback).
// ---------------------------------------------------------------------------
__global__ __launch_bounds__(256)
void vconv_kernel(const float* __restrict__ W, const float* __restrict__ bias,
                  const float* __restrict__ x, float* __restrict__ out,
                  const float* __restrict__ gamma)
{
    if (gamma[0] == 0.0f) return;
    const int b  = blockIdx.z;
    const int m0 = blockIdx.y * 128;
    const int n0 = blockIdx.x * 128;

    __shared__ float As[8][128];
    __shared__ float Bs[8][128];

    const int tid = threadIdx.x;
    const int tx = tid % 16, ty = tid / 16;
    const float* xb = x + (size_t)b * Cc * Ll;

    const int aRow = tid >> 1;
    const int aCol = (tid & 1) * 4;
    const int bRow = tid >> 5;
    const int bCol = (tid & 31) * 4;

    float acc[8][8];
    #pragma unroll
    for (int i = 0; i < 8; i++)
        #pragma unroll
        for (int j = 0; j < 8; j++) acc[i][j] = 0.0f;

    for (int k0 = 0; k0 < Cc; k0 += 8) {
        float4 a = *(const float4*)&W[(size_t)(m0 + aRow) * Cc + k0 + aCol];
        As[aCol + 0][aRow] = a.x;
        As[aCol + 1][aRow] = a.y;
        As[aCol + 2][aRow] = a.z;
        As[aCol + 3][aRow] = a.w;
        *(float4*)&Bs[bRow][bCol] =
            *(const float4*)&xb[(size_t)(k0 + bRow) * Ll + n0 + bCol];
        __syncthreads();

        #pragma unroll
        for (int k = 0; k < 8; k++) {
            float rm[8], rn[8];
            #pragma unroll
            for (int i = 0; i < 8; i++) rm[i] = As[k][ty * 8 + i];
            #pragma unroll
            for (int j = 0; j < 8; j++) rn[j] = Bs[k][tx * 8 + j];
            #pragma unroll
            for (int i = 0; i < 8; i++)
                #pragma unroll
                for (int j = 0; j < 8; j++)
                    acc[i][j] = fmaf(rm[i], rn[j], acc[i][j]);
        }
        __syncthreads();
    }

    float* ob = out + (size_t)b * Cc * Ll;
    #pragma unroll
    for (int i = 0; i < 8; i++) {
        const int m = m0 + ty * 8 + i;
        const float bb = bias[m];
        float* po = ob + (size_t)m * Ll + n0 + tx * 8;
        *(float4*)po = make_float4(acc[i][0] + bb, acc[i][1] + bb,
                                   acc[i][2] + bb, acc[i][3] + bb);
        *(float4*)(po + 4) = make_float4(acc[i][4] + bb, acc[i][5] + bb,
                                         acc[i][6] + bb, acc[i][7] + bb);
    }
}

__global__ __launch_bounds__(256)
void outgemm_kernel(const float* __restrict__ att, const float* __restrict__ x,
                    float* __restrict__ out, const float* __restrict__ gamma)
{
    const float g = gamma[0];
    if (g == 0.0f) return;
    const int b  = blockIdx.z;
    const int c0 = blockIdx.y * 128;
    const int i0 = blockIdx.x * 128;

    __shared__ float Vs[8][128];
    __shared__ float Ts[8][128];

    const int tid = threadIdx.x;
    const int tx = tid % 16, ty = tid / 16;
    const int aRow = tid >> 1;
    const int aCol = (tid & 1) * 4;

    const float* vb = g_v + (size_t)b * Cc * Ll;
    const float* ab = att + (size_t)b * Ll * Ll;

    float acc[8][8];
    #pragma unroll
    for (int i = 0; i < 8; i++)
        #pragma unroll
        for (int j = 0; j < 8; j++) acc[i][j] = 0.0f;

    for (int j0 = 0; j0 < Ll; j0 += 8) {
        float4 a = *(const float4*)&vb[(size_t)(c0 + aRow) * Ll + j0 + aCol];
        Vs[aCol + 0][aRow] = a.x;
        Vs[aCol + 1][aRow] = a.y;
        Vs[aCol + 2][aRow] = a.z;
        Vs[aCol + 3][aRow] = a.w;
        float4 tt = *(const float4*)&ab[(size_t)(i0 + aRow) * Ll + j0 + aCol];
        Ts[aCol + 0][aRow] = tt.x;
        Ts[aCol + 1][aRow] = tt.y;
        Ts[aCol + 2][aRow] = tt.z;
        Ts[aCol + 3][aRow] = tt.w;
        __syncthreads();

        #pragma unroll
        for (int k = 0; k < 8; k++) {
            float rm[8], rn[8];
            #pragma unroll
            for (int i = 0; i < 8; i++) rm[i] = Vs[k][ty * 8 + i];
            #pragma unroll
            for (int j = 0; j < 8; j++) rn[j] = Ts[k][tx * 8 + j];
            #pragma unroll
            for (int i = 0; i < 8; i++)
                #pragma unroll
                for (int j = 0; j < 8; j++)
                    acc[i][j] = fmaf(rm[i], rn[j], acc[i][j]);
        }
        __syncthreads();
    }

    #pragma unroll
    for (int i = 0; i < 8; i++) {
        const size_t off = (size_t)b * Cc * Ll + (size_t)(c0 + ty * 8 + i) * Ll
                         + i0 + tx * 8;
        #pragma unroll
        for (int j = 0; j < 8; j++)
            out[off + j] = g * acc[i][j] + x[off + j];
    }
}

// ---------------------------------------------------------------------------
extern "C" void kernel_launch(void* const* d_in, const int* in_sizes, int n_in,
                              void* d_out, int out_size)
{
    (void)in_sizes; (void)n_in;
    const float* x     = (const float*)d_in[0];
    const float* q_w   = (const float*)d_in[1];
    const float* q_b   = (const float*)d_in[2];
    const float* k_w   = (const float*)d_in[3];
    const float* k_b   = (const float*)d_in[4];
    const float* v_w   = (const float*)d_in[5];
    const float* v_b   = (const float*)d_in[6];
    const float* gamma = (const float*)d_in[7];

    const size_t BCL = (size_t)Bb * Cc * Ll;        // 8388608
    const size_t BLL = (size_t)Bb * Ll * Ll;        // 33554432

    float* out_ptr;
    float* att_ptr;
    if ((size_t)out_size >= BCL + BLL) {
        out_ptr = (float*)d_out;
        att_ptr = (float*)d_out + BCL;
    } else if ((size_t)out_size == BLL) {
        cudaGetSymbolAddress((void**)&out_ptr, g_outbuf);
        att_ptr = (float*)d_out;
    } else {
        out_ptr = (float*)d_out;
        cudaGetSymbolAddress((void**)&att_ptr, g_att);
    }
    float* vbuf; cudaGetSymbolAddress((void**)&vbuf, g_v);

    static int smem_set = 0;
    if (!smem_set) {
        cudaFuncSetAttribute(energy_mma_kernel,
                             cudaFuncAttributeMaxDynamicSharedMemorySize,
                             MMA_SMEM_B);
        cudaFuncSetAttribute(qkconv_mma_kernel,
                             cudaFuncAttributeMaxDynamicSharedMemorySize,
                             MMA_SMEM_B);
        smem_set = 1;
    }

    dim3 blk(256);

    // split inputs for tensor-core path (xsplit also does out=x when gamma==0)
    wsplit_kernel<<<dim3(CQq, 2), dim3(128)>>>(q_w, k_w);
    xsplit_kernel<<<dim3(Ll / 64, Cc / 64, Bb), blk>>>(x, out_ptr, gamma);

    // q and k projections on tensor cores -> split bf16 [pos][d]
    qkconv_mma_kernel<<<dim3(Ll / 128, 2, Bb), blk, MMA_SMEM_B>>>(q_b, k_b);

    // energy on tensor cores -> attention region, softmax in place
    energy_mma_kernel<<<dim3(Ll / 128, Ll / 128, Bb), blk, MMA_SMEM_B>>>(att_ptr);
    softmax_kernel<<<dim3(Bb * Ll), blk>>>(att_ptr);

    // gamma != 0 fallback path (no-ops when gamma == 0)
    vconv_kernel<<<dim3(Ll / 128, Cc / 128, Bb), blk>>>(v_w, v_b, x, vbuf, gamma);
    outgemm_kernel<<<dim3(Ll / 128, Cc / 128, Bb), blk>>>(att_ptr, x, out_ptr, gamma);
}

// round 13
// speedup vs baseline: 1.0638x; 1.0082x over previous
#include <cuda_runtime.h>
#include <cuda_bf16.h>
#include <stdint.h>
#include <math.h>

#define Bb 8
#define Cc 512
#define Ll 2048
#define CQq 128

// Static device scratch (allocation-free rule: __device__ globals).
__device__ __nv_bfloat16 g_xhi[(size_t)Bb * Ll * Cc];    // x^T split hi [b][pos][c]
__device__ __nv_bfloat16 g_xlo[(size_t)Bb * Ll * Cc];
__device__ __nv_bfloat16 g_wqhi[CQq * Cc];
__device__ __nv_bfloat16 g_wqlo[CQq * Cc];
__device__ __nv_bfloat16 g_wkhi[CQq * Cc];
__device__ __nv_bfloat16 g_wklo[CQq * Cc];
__device__ __nv_bfloat16 g_qhi[(size_t)Bb * Ll * CQq];   // [b][pos][d]
__device__ __nv_bfloat16 g_qlo[(size_t)Bb * Ll * CQq];
__device__ __nv_bfloat16 g_khi[(size_t)Bb * Ll * CQq];
__device__ __nv_bfloat16 g_klo[(size_t)Bb * Ll * CQq];
__device__ float g_v[(size_t)Bb * Cc * Ll];              // gamma!=0 path only
__device__ float g_att[(size_t)Bb * Ll * Ll];            // fallback
__device__ float g_outbuf[(size_t)Bb * Cc * Ll];         // fallback

// 32-wide K chunks in smem, pitch 40 bf16 (80B = 20 words): ldmatrix 8-row x
// 16B reads cover all 32 banks (20r mod 32 pattern) -> conflict-free.
#define KPAD 40
#define T32 (128 * KPAD)              // 5120 bf16 per tile
#define STAGE_B (4 * T32 * 2)         // 40960 bytes (Ahi,Alo,Bhi,Blo)
#define MMA_SMEM_B (2 * STAGE_B)      // 81920 bytes (2 stages)

// ---------------------------------------------------------------------------
// Split W (CQ x C fp32) into bf16 hi/lo. grid (128, 2), block 128.
// ---------------------------------------------------------------------------
__global__ __launch_bounds__(128)
void wsplit_kernel(const float* __restrict__ q_w, const float* __restrict__ k_w)
{
    const int row = blockIdx.x;
    const int s   = blockIdx.y;
    const float* W = s ? k_w : q_w;
    __nv_bfloat16* ho = s ? g_wkhi : g_wqhi;
    __nv_bfloat16* lo = s ? g_wklo : g_wqlo;

    const int c = threadIdx.x * 4;
    float4 v = *(const float4*)&W[(size_t)row * Cc + c];
    __nv_bfloat16 h[4], l[4];
    float vv[4] = {v.x, v.y, v.z, v.w};
    #pragma unroll
    for (int i = 0; i < 4; i++) {
        h[i] = __float2bfloat16_rn(vv[i]);
        l[i] = __float2bfloat16_rn(vv[i] - __bfloat162float(h[i]));
    }
    *(uint2*)&ho[(size_t)row * Cc + c] = *(uint2*)h;
    *(uint2*)&lo[(size_t)row * Cc + c] = *(uint2*)l;
}

// ---------------------------------------------------------------------------
// Transpose + split x: [b][c][l] fp32 -> [b][l][c] bf16 hi/lo.
// FUSED: when gamma==0, also writes out = x (saves a separate copy kernel).
// ---------------------------------------------------------------------------
__global__ __launch_bounds__(256)
void xsplit_kernel(const float* __restrict__ x, float* __restrict__ out,
                   const float* __restrict__ gamma)
{
    __shared__ float ts[64][65];
    const int b  = blockIdx.z;
    const int l0 = blockIdx.x * 64;
    const int c0 = blockIdx.y * 64;
    const int tid = threadIdx.x;
    const bool docopy = (gamma[0] == 0.0f);

    const float* xb = x + (size_t)b * Cc * Ll;
    float* ob = out + (size_t)b * Cc * Ll;
    const int ly = tid >> 4;          // 0..15
    const int lx = (tid & 15) * 4;    // 0..60
    #pragma unroll
    for (int rr = 0; rr < 4; rr++) {
        const int cl = ly + rr * 16;
        float4 v = *(const float4*)&xb[(size_t)(c0 + cl) * Ll + l0 + lx];
        if (docopy)
            *(float4*)&ob[(size_t)(c0 + cl) * Ll + l0 + lx] = v;
        ts[cl][lx + 0] = v.x;
        ts[cl][lx + 1] = v.y;
        ts[cl][lx + 2] = v.z;
        ts[cl][lx + 3] = v.w;
    }
    __syncthreads();

    __nv_bfloat16* xh = g_xhi + (size_t)b * Ll * Cc;
    __nv_bfloat16* xl = g_xlo + (size_t)b * Ll * Cc;
    const int wy = tid >> 3;          // 0..31
    const int wx = (tid & 7) * 8;     // 0..56
    #pragma unroll
    for (int rr = 0; rr < 2; rr++) {
        const int ll = wy + rr * 32;
        __nv_bfloat16 h[8], l[8];
        #pragma unroll
        for (int e = 0; e < 8; e++) {
            float v = ts[wx + e][ll];
            h[e] = __float2bfloat16_rn(v);
            l[e] = __float2bfloat16_rn(v - __bfloat162float(h[e]));
        }
        *(uint4*)&xh[(size_t)(l0 + ll) * Cc + c0 + wx] = *(uint4*)h;
        *(uint4*)&xl[(size_t)(l0 + ll) * Cc + c0 + wx] = *(uint4*)l;
    }
}

// ---------------------------------------------------------------------------
// mma / ldmatrix / cp.async helpers
// ---------------------------------------------------------------------------
__device__ __forceinline__ void mma16816(float* acc, const uint32_t* a,
                                         const uint32_t* bfr)
{
    asm volatile(
        "mma.sync.aligned.m16n8k16.row.col.f32.bf16.bf16.f32 "
        "{%0,%1,%2,%3}, {%4,%5,%6,%7}, {%8,%9}, {%0,%1,%2,%3};\n"
        : "+f"(acc[0]), "+f"(acc[1]), "+f"(acc[2]), "+f"(acc[3])
        : "r"(a[0]), "r"(a[1]), "r"(a[2]), "r"(a[3]),
          "r"(bfr[0]), "r"(bfr[1]));
}

__device__ __forceinline__ void ldsm_x4(uint32_t* r, uint32_t addr)
{
    asm volatile(
        "ldmatrix.sync.aligned.m8n8.x4.shared.b16 {%0,%1,%2,%3}, [%4];\n"
        : "=r"(r[0]), "=r"(r[1]), "=r"(r[2]), "=r"(r[3]) : "r"(addr));
}

__device__ __forceinline__ void cp16(uint32_t dst, const void* src)
{
    asm volatile("cp.async.cg.shared.global [%0], [%1], 16;\n"
                 :: "r"(dst), "l"(src));
}
// wait_all == commit_group + wait_group 0 (waits every outstanding cp.async)
#define CP_WAIT_ALL() asm volatile("cp.async.wait_all;\n" ::: "memory")

// per-lane ldmatrix offsets (bf16-element units, relative to tile base)
__device__ __forceinline__ uint32_t a_frag_off(int wm, int lane)
{
    return (uint32_t)((wm * 64 + (lane & 15)) * KPAD + ((lane >> 4) << 3));
}
__device__ __forceinline__ uint32_t b_frag_off(int wn, int lane)
{
    return (uint32_t)((wn * 32 + ((lane >> 4) << 3) + (lane & 7)) * KPAD
                      + (((lane >> 3) & 1) << 3));
}

// ---------------------------------------------------------------------------
// cp.async loads for one 32-wide K chunk (4 tiles: Ahi,Alo,Bhi,Blo).
// Each thread: 2 iterations x 4 tiles x 16B = 128B.
// ---------------------------------------------------------------------------
__device__ __forceinline__ void load_chunk32(
    uint32_t stageU, int tid,
    const __nv_bfloat16* aH, const __nv_bfloat16* aL,
    const __nv_bfloat16* bH, const __nv_bfloat16* bL,
    int rowA, int rowB, int stride, int c0)
{
    #pragma unroll
    for (int q = 0; q < 2; q++) {
        const int idx = q * 256 + tid;
        const int r  = idx >> 2;          // 0..127
        const int cc = (idx & 3) * 8;     // 0..24
        const uint32_t d = stageU + (uint32_t)((r * KPAD + cc) * 2);
        cp16(d,               aH + (size_t)(rowA + r) * stride + c0 + cc);
        cp16(d + T32 * 2,     aL + (size_t)(rowA + r) * stride + c0 + cc);
        cp16(d + 2 * T32 * 2, bH + (size_t)(rowB + r) * stride + c0 + cc);
        cp16(d + 3 * T32 * 2, bL + (size_t)(rowB + r) * stride + c0 + cc);
    }
}

// ---------------------------------------------------------------------------
// Compute one 32-wide chunk: 2 k-steps, 3-combo split bf16, ldmatrix frags.
// ---------------------------------------------------------------------------
__device__ __forceinline__ void kchunk32_mma(
    uint32_t stageU, uint32_t a_off, uint32_t b_off, float acc[4][4][4])
{
    const uint32_t AhiU = stageU;
    const uint32_t AloU = stageU + T32 * 2;
    const uint32_t BhiU = stageU + 2 * T32 * 2;
    const uint32_t BloU = stageU + 3 * T32 * 2;
    #pragma unroll
    for (int ks = 0; ks < 2; ks++) {
        const int k0 = ks * 16;
        uint32_t bh[2][4], bl[2][4];   // [pair p][4 regs = bn=2p, 2p+1]
        #pragma unroll
        for (int p = 0; p < 2; p++) {
            const uint32_t bo = 2u * (b_off + (uint32_t)(p * 16 * KPAD + k0));
            ldsm_x4(bh[p], BhiU + bo);
            ldsm_x4(bl[p], BloU + bo);
        }
        #pragma unroll
        for (int am = 0; am < 4; am++) {
            const uint32_t ao = 2u * (a_off + (uint32_t)(am * 16 * KPAD + k0));
            uint32_t ah[4], al[4];
            ldsm_x4(ah, AhiU + ao);
            ldsm_x4(al, AloU + ao);
            #pragma unroll
            for (int bn = 0; bn < 4; bn++) {
                const uint32_t* bhp = &bh[bn >> 1][(bn & 1) * 2];
                const uint32_t* blp = &bl[bn >> 1][(bn & 1) * 2];
                mma16816(acc[am][bn], ah, bhp);
                mma16816(acc[am][bn], ah, blp);
                mma16816(acc[am][bn], al, bhp);
            }
        }
    }
}

// ---------------------------------------------------------------------------
// 2-stage pipelined mainloop. ONE sync per chunk:
//   wait(chunk it) -> sync -> issue(chunk it+1 into other stage) -> compute(it)
// Overwrite hazard safe: stage being filled held chunk it-1, whose compute
// finished before this iteration's sync.
// ---------------------------------------------------------------------------
template <int NCHUNK>
__device__ __forceinline__ void mma_mainloop(
    uint32_t smU, int tid,
    const __nv_bfloat16* aH, const __nv_bfloat16* aL,
    const __nv_bfloat16* bH, const __nv_bfloat16* bL,
    int rowA, int rowB, int stride,
    uint32_t a_off, uint32_t b_off, float acc[4][4][4])
{
    load_chunk32(smU, tid, aH, aL, bH, bL, rowA, rowB, stride, 0);
    #pragma unroll
    for (int it = 0; it < NCHUNK; it++) {
        CP_WAIT_ALL();
        __syncthreads();
        if (it + 1 < NCHUNK)
            load_chunk32(smU + (uint32_t)(((it + 1) & 1) * STAGE_B), tid,
                         aH, aL, bH, bL, rowA, rowB, stride, (it + 1) * 32);
        kchunk32_mma(smU + (uint32_t)((it & 1) * STAGE_B), a_off, b_off, acc);
    }
}

// ---------------------------------------------------------------------------
// q/k conv on tensor cores: out[pos][d] = sum_c xT[pos][c]*W[d][c] + bias[d]
// grid (L/128, 2 {q,k}, B), block 256 (8 warps, 2m x 4n), K=512 (16 chunks).
// ---------------------------------------------------------------------------
__global__ __launch_bounds__(256, 2)
void qkconv_mma_kernel(const float* __restrict__ q_b, const float* __restrict__ k_b)
{
    extern __shared__ __nv_bfloat16 sm[];
    __shared__ float sbias[128];

    const int p0 = blockIdx.x * 128;
    const int s  = blockIdx.y;
    const int b  = blockIdx.z;

    const __nv_bfloat16* whi = s ? g_wkhi : g_wqhi;
    const __nv_bfloat16* wlo = s ? g_wklo : g_wqlo;
    const float* bias = s ? k_b : q_b;

    const int tid  = threadIdx.x;
    const int lane = tid & 31;
    const int wid  = tid >> 5;
    const int wm   = wid >> 2;
    const int wn   = wid & 3;
    const int g    = lane >> 2;
    const int t    = lane & 3;

    if (tid < 128) sbias[tid] = bias[tid];

    const uint32_t smU = (uint32_t)__cvta_generic_to_shared(sm);
    const uint32_t a_off = a_frag_off(wm, lane);
    const uint32_t b_off = b_frag_off(wn, lane);

    const __nv_bfloat16* xh = g_xhi + (size_t)b * Ll * Cc;
    const __nv_bfloat16* xl = g_xlo + (size_t)b * Ll * Cc;

    float acc[4][4][4];
    #pragma unroll
    for (int am = 0; am < 4; am++)
        #pragma unroll
        for (int bn = 0; bn < 4; bn++)
            #pragma unroll
            for (int c = 0; c < 4; c++) acc[am][bn][c] = 0.0f;

    mma_mainloop<16>(smU, tid, xh, xl, whi, wlo, p0, 0, Cc,
                     a_off, b_off, acc);

    __nv_bfloat16* hb = (s ? g_khi : g_qhi) + (size_t)b * Ll * CQq;
    __nv_bfloat16* lb = (s ? g_klo : g_qlo) + (size_t)b * Ll * CQq;
    #pragma unroll
    for (int am = 0; am < 4; am++) {
        const int r0 = wm * 64 + am * 16 + g;
        #pragma unroll
        for (int bn = 0; bn < 4; bn++) {
            const int col = wn * 32 + bn * 8 + 2 * t;
            const float b0 = sbias[col], b1 = sbias[col + 1];
            #pragma unroll
            for (int half = 0; half < 2; half++) {
                const int row = r0 + half * 8;
                const float v0 = acc[am][bn][half * 2 + 0] + b0;
                const float v1 = acc[am][bn][half * 2 + 1] + b1;
                __nv_bfloat16 h0 = __float2bfloat16_rn(v0);
                __nv_bfloat16 h1 = __float2bfloat16_rn(v1);
                __nv_bfloat16 l0 = __float2bfloat16_rn(v0 - __bfloat162float(h0));
                __nv_bfloat16 l1 = __float2bfloat16_rn(v1 - __bfloat162float(h1));
                *(__nv_bfloat162*)&hb[(size_t)(p0 + row) * CQq + col] =
                    __halves2bfloat162(h0, h1);
                *(__nv_bfloat162*)&lb[(size_t)(p0 + row) * CQq + col] =
                    __halves2bfloat162(l0, l1);
            }
        }
    }
}

// ---------------------------------------------------------------------------
// energy[b,i,j] = sum_d q[b,i,d]*k[b,j,d], K=128 (4 chunks), pipelined.
// ---------------------------------------------------------------------------
__global__ __launch_bounds__(256, 2)
void energy_mma_kernel(float* __restrict__ E)
{
    extern __shared__ __nv_bfloat16 sm[];

    const int b  = blockIdx.z;
    const int i0 = blockIdx.y * 128;
    const int j0 = blockIdx.x * 128;

    const int tid  = threadIdx.x;
    const int lane = tid & 31;
    const int wid  = tid >> 5;
    const int wm   = wid >> 2;
    const int wn   = wid & 3;
    const int g    = lane >> 2;
    const int t    = lane & 3;

    const uint32_t smU = (uint32_t)__cvta_generic_to_shared(sm);
    const uint32_t a_off = a_frag_off(wm, lane);
    const uint32_t b_off = b_frag_off(wn, lane);

    const size_t boff = (size_t)b * Ll * CQq;

    float acc[4][4][4];
    #pragma unroll
    for (int am = 0; am < 4; am++)
        #pragma unroll
        for (int bn = 0; bn < 4; bn++)
            #pragma unroll
            for (int c = 0; c < 4; c++) acc[am][bn][c] = 0.0f;

    mma_mainloop<4>(smU, tid, g_qhi + boff, g_qlo + boff,
                    g_khi + boff, g_klo + boff, i0, j0, CQq,
                    a_off, b_off, acc);

    float* eb = E + (size_t)b * Ll * Ll;
    #pragma unroll
    for (int am = 0; am < 4; am++) {
        const int row = i0 + wm * 64 + am * 16 + g;
        #pragma unroll
        for (int bn = 0; bn < 4; bn++) {
            const int col = j0 + wn * 32 + bn * 8 + 2 * t;
            *(float2*)&eb[(size_t)row * Ll + col] =
                make_float2(acc[am][bn][0], acc[am][bn][1]);
            *(float2*)&eb[(size_t)(row + 8) * Ll + col] =
                make_float2(acc[am][bn][2], acc[am][bn][3]);
        }
    }
}

// ---------------------------------------------------------------------------
// In-place row softmax, float4 loads + warp-shuffle reductions.
// ---------------------------------------------------------------------------
__global__ __launch_bounds__(256)
void softmax_kernel(float* __restrict__ att)
{
    const size_t row = blockIdx.x;
    float4* p = (float4*)(att + row * (size_t)Ll);
    const int tid = threadIdx.x;
    const int lane = tid & 31, wrp = tid >> 5;

    float4 v0 = p[tid];
    float4 v1 = p[tid + 256];

    float m = fmaxf(fmaxf(fmaxf(v0.x, v0.y), fmaxf(v0.z, v0.w)),
                    fmaxf(fmaxf(v1.x, v1.y), fmaxf(v1.z, v1.w)));
    #pragma unroll
    for (int s = 16; s > 0; s >>= 1)
        m = fmaxf(m, __shfl_xor_sync(0xffffffffu, m, s));

    __shared__ float red[8];
    if (lane == 0) red[wrp] = m;
    __syncthreads();
    float bm = red[lane & 7];
    #pragma unroll
    for (int s = 4; s > 0; s >>= 1)
        bm = fmaxf(bm, __shfl_xor_sync(0xffffffffu, bm, s));
    m = __shfl_sync(0xffffffffu, bm, 0);

    v0.x = __expf(v0.x - m); v0.y = __expf(v0.y - m);
    v0.z = __expf(v0.z - m); v0.w = __expf(v0.w - m);
    v1.x = __expf(v1.x - m); v1.y = __expf(v1.y - m);
    v1.z = __expf(v1.z - m); v1.w = __expf(v1.w - m);

    float sum = v0.x + v0.y + v0.z + v0.w + v1.x + v1.y + v1.z + v1.w;
    #pragma unroll
    for (int s = 16; s > 0; s >>= 1)
        sum += __shfl_xor_sync(0xffffffffu, sum, s);
    __syncthreads();
    if (lane == 0) red[wrp] = sum;
    __syncthreads();
    float bs = red[lane & 7];
    #pragma unroll
    for (int s = 4; s > 0; s >>= 1)
        bs += __shfl_xor_sync(0xffffffffu, bs, s);
    const float inv = 1.0f / __shfl_sync(0xffffffffu, bs, 0);

    v0.x *= inv; v0.y *= inv; v0.z *= inv; v0.w *= inv;
    v1.x *= inv; v1.y *= inv; v1.z *= inv; v1.w *= inv;
    p[tid]       = v0;
    p[tid + 256] = v1;
}

// ---------------------------------------------------------------------------
// gamma != 0 path kernels (gated; full-precision fallback).
// ---------------------------------------------------------------------------
__global__ __launch_bounds__(256)
void vconv_kernel(const float* __restrict__ W, const float* __restrict__ bias,
                  const float* __restrict__ x, float* __restrict__ out,
                  const float* __restrict__ gamma)
{
    if (gamma[0] == 0.0f) return;
    const int b  = blockIdx.z;
    const int m0 = blockIdx.y * 128;
    const int n0 = blockIdx.x * 128;

    __shared__ float As[8][128];
    __shared__ float Bs[8][128];

    const int tid = threadIdx.x;
    const int tx = tid % 16, ty = tid / 16;
    const float* xb = x + (size_t)b * Cc * Ll;

    const int aRow = tid >> 1;
    const int aCol = (tid & 1) * 4;
    const int bRow = tid >> 5;
    const int bCol = (tid & 31) * 4;

    float acc[8][8];
    #pragma unroll
    for (int i = 0; i < 8; i++)
        #pragma unroll
        for (int j = 0; j < 8; j++) acc[i][j] = 0.0f;

    for (int k0 = 0; k0 < Cc; k0 += 8) {
        float4 a = *(const float4*)&W[(size_t)(m0 + aRow) * Cc + k0 + aCol];
        As[aCol + 0][aRow] = a.x;
        As[aCol + 1][aRow] = a.y;
        As[aCol + 2][aRow] = a.z;
        As[aCol + 3][aRow] = a.w;
        *(float4*)&Bs[bRow][bCol] =
            *(const float4*)&xb[(size_t)(k0 + bRow) * Ll + n0 + bCol];
        __syncthreads();

        #pragma unroll
        for (int k = 0; k < 8; k++) {
            float rm[8], rn[8];
            #pragma unroll
            for (int i = 0; i < 8; i++) rm[i] = As[k][ty * 8 + i];
            #pragma unroll
            for (int j = 0; j < 8; j++) rn[j] = Bs[k][tx * 8 + j];
            #pragma unroll
            for (int i = 0; i < 8; i++)
                #pragma unroll
                for (int j = 0; j < 8; j++)
                    acc[i][j] = fmaf(rm[i], rn[j], acc[i][j]);
        }
        __syncthreads();
    }

    float* ob = out + (size_t)b * Cc * Ll;
    #pragma unroll
    for (int i = 0; i < 8; i++) {
        const int m = m0 + ty * 8 + i;
        const float bb = bias[m];
        float* po = ob + (size_t)m * Ll + n0 + tx * 8;
        *(float4*)po = make_float4(acc[i][0] + bb, acc[i][1] + bb,
                                   acc[i][2] + bb, acc[i][3] + bb);
        *(float4*)(po + 4) = make_float4(acc[i][4] + bb, acc[i][5] + bb,
                                         acc[i][6] + bb, acc[i][7] + bb);
    }
}

__global__ __launch_bounds__(256)
void outgemm_kernel(const float* __restrict__ att, const float* __restrict__ x,
                    float* __restrict__ out, const float* __restrict__ gamma)
{
    const float g = gamma[0];
    if (g == 0.0f) return;
    const int b  = blockIdx.z;
    const int c0 = blockIdx.y * 128;
    const int i0 = blockIdx.x * 128;

    __shared__ float Vs[8][128];
    __shared__ float Ts[8][128];

    const int tid = threadIdx.x;
    const int tx = tid % 16, ty = tid / 16;
    const int aRow = tid >> 1;
    const int aCol = (tid & 1) * 4;

    const float* vb = g_v + (size_t)b * Cc * Ll;
    const float* ab = att + (size_t)b * Ll * Ll;

    float acc[8][8];
    #pragma unroll
    for (int i = 0; i < 8; i++)
        #pragma unroll
        for (int j = 0; j < 8; j++) acc[i][j] = 0.0f;

    for (int j0 = 0; j0 < Ll; j0 += 8) {
        float4 a = *(const float4*)&vb[(size_t)(c0 + aRow) * Ll + j0 + aCol];
        Vs[aCol + 0][aRow] = a.x;
        Vs[aCol + 1][aRow] = a.y;
        Vs[aCol + 2][aRow] = a.z;
        Vs[aCol + 3][aRow] = a.w;
        float4 tt = *(const float4*)&ab[(size_t)(i0 + aRow) * Ll + j0 + aCol];
        Ts[aCol + 0][aRow] = tt.x;
        Ts[aCol + 1][aRow] = tt.y;
        Ts[aCol + 2][aRow] = tt.z;
        Ts[aCol + 3][aRow] = tt.w;
        __syncthreads();

        #pragma unroll
        for (int k = 0; k < 8; k++) {
            float rm[8], rn[8];
            #pragma unroll
            for (int i = 0; i < 8; i++) rm[i] = Vs[k][ty * 8 + i];
            #pragma unroll
            for (int j = 0; j < 8; j++) rn[j] = Ts[k][tx * 8 + j];
            #pragma unroll
            for (int i = 0; i < 8; i++)
                #pragma unroll
                for (int j = 0; j < 8; j++)
                    acc[i][j] = fmaf(rm[i], rn[j], acc[i][j]);
        }
        __syncthreads();
    }

    #pragma unroll
    for (int i = 0; i < 8; i++) {
        const size_t off = (size_t)b * Cc * Ll + (size_t)(c0 + ty * 8 + i) * Ll
                         + i0 + tx * 8;
        #pragma unroll
        for (int j = 0; j < 8; j++)
            out[off + j] = g * acc[i][j] + x[off + j];
    }
}

// ---------------------------------------------------------------------------
extern "C" void kernel_launch(void* const* d_in, const int* in_sizes, int n_in,
                              void* d_out, int out_size)
{
    (void)in_sizes; (void)n_in;
    const float* x     = (const float*)d_in[0];
    const float* q_w   = (const float*)d_in[1];
    const float* q_b   = (const float*)d_in[2];
    const float* k_w   = (const float*)d_in[3];
    const float* k_b   = (const float*)d_in[4];
    const float* v_w   = (const float*)d_in[5];
    const float* v_b   = (const float*)d_in[6];
    const float* gamma = (const float*)d_in[7];

    const size_t BCL = (size_t)Bb * Cc * Ll;        // 8388608
    const size_t BLL = (size_t)Bb * Ll * Ll;        // 33554432

    float* out_ptr;
    float* att_ptr;
    if ((size_t)out_size >= BCL + BLL) {
        out_ptr = (float*)d_out;
        att_ptr = (float*)d_out + BCL;
    } else if ((size_t)out_size == BLL) {
        cudaGetSymbolAddress((void**)&out_ptr, g_outbuf);
        att_ptr = (float*)d_out;
    } else {
        out_ptr = (float*)d_out;
        cudaGetSymbolAddress((void**)&att_ptr, g_att);
    }
    float* vbuf; cudaGetSymbolAddress((void**)&vbuf, g_v);

    static int smem_set = 0;
    if (!smem_set) {
        cudaFuncSetAttribute(energy_mma_kernel,
                             cudaFuncAttributeMaxDynamicSharedMemorySize,
                             MMA_SMEM_B);
        cudaFuncSetAttribute(qkconv_mma_kernel,
                             cudaFuncAttributeMaxDynamicSharedMemorySize,
                             MMA_SMEM_B);
        smem_set = 1;
    }

    dim3 blk(256);

    // split inputs for tensor-core path (xsplit also does out=x when gamma==0)
    wsplit_kernel<<<dim3(CQq, 2), dim3(128)>>>(q_w, k_w);
    xsplit_kernel<<<dim3(Ll / 64, Cc / 64, Bb), blk>>>(x, out_ptr, gamma);

    // q and k projections on tensor cores -> split bf16 [pos][d]
    qkconv_mma_kernel<<<dim3(Ll / 128, 2, Bb), blk, MMA_SMEM_B>>>(q_b, k_b);

    // energy on tensor cores -> attention region, softmax in place
    energy_mma_kernel<<<dim3(Ll / 128, Ll / 128, Bb), blk, MMA_SMEM_B>>>(att_ptr);
    softmax_kernel<<<dim3(Bb * Ll), blk>>>(att_ptr);

    // gamma != 0 fallback path (no-ops when gamma == 0)
    vconv_kernel<<<dim3(Ll / 128, Cc / 128, Bb), blk>>>(v_w, v_b, x, vbuf, gamma);
    outgemm_kernel<<<dim3(Ll / 128, Cc / 128, Bb), blk>>>(att_ptr, x, out_ptr, gamma);
}